// round 15
// baseline (speedup 1.0000x reference)
#include <cuda_runtime.h>
#include <cuda_fp16.h>
#include <cstdint>

#define NN 50000
#define EE 800000
#define SLOT 96          // fixed CSR slots per node; P(deg>=96) ~ 1e-40 at mean 16

// ---------------- scratch (device globals) ----------------------------------
__device__ __align__(16) float  g_q1 [NN*128];
__device__ __align__(16) __half g_kv1[NN*256];   // per node: k[0..127] | v[0..127]
__device__ __align__(16) float  g_sk1[NN*128];
__device__ __align__(16) float  g_h  [NN*128];
__device__ __align__(16) float  g_q2 [NN*64];
__device__ __align__(16) __half g_kv2[NN*128];   // per node: k[0..63] | v[0..63]
__device__ __align__(16) float  g_sk2[NN*64];
__device__ __align__(16) int g_cnt[NN];
__device__ int g_csr[NN * SLOT];   // src ids, bucketed by dst (zero-init -> always in [0,NN))

// ---------------- CSR build: memset + ONE scatter pass -----------------------
__global__ void csr_scatter4(const int4* __restrict__ src4, const int4* __restrict__ dst4) {
    int i = blockIdx.x * blockDim.x + threadIdx.x;
    if (i >= EE / 4) return;
    int4 s = src4[i];
    int4 d = dst4[i];
    g_csr[d.x * SLOT + atomicAdd(&g_cnt[d.x], 1)] = s.x;
    g_csr[d.y * SLOT + atomicAdd(&g_cnt[d.y], 1)] = s.y;
    g_csr[d.z * SLOT + atomicAdd(&g_cnt[d.z], 1)] = s.z;
    g_csr[d.w * SLOT + atomicAdd(&g_cnt[d.w], 1)] = s.w;
}

// ---------------- tf32 helpers ----------------------------------------------
__device__ __forceinline__ float to_tf32(float x) {
    uint32_t u;
    asm("cvt.rna.tf32.f32 %0, %1;" : "=r"(u) : "f"(x));
    return __uint_as_float(u);
}
__device__ __forceinline__ void mma_tf32(float c[4],
                                         uint32_t a0, uint32_t a1, uint32_t a2, uint32_t a3,
                                         uint32_t b0, uint32_t b1) {
    asm volatile("mma.sync.aligned.m16n8k8.row.col.f32.tf32.tf32.f32 "
                 "{%0,%1,%2,%3}, {%4,%5,%6,%7}, {%8,%9}, {%0,%1,%2,%3};"
                 : "+f"(c[0]), "+f"(c[1]), "+f"(c[2]), "+f"(c[3])
                 : "r"(a0), "r"(a1), "r"(a2), "r"(a3), "r"(b0), "r"(b1));
}

// ---------------- compile-time epilogue store -------------------------------
template <bool ISH, int LDC>
__device__ __forceinline__ void store2(void* C, int row, int col, float v0, float v1) {
    if (ISH) {
        __half* Ch = reinterpret_cast<__half*>(C);
        *reinterpret_cast<__half2*>(Ch + (size_t)row * LDC + col) = __floats2half2_rn(v0, v1);
    } else {
        float* Cf = reinterpret_cast<float*>(C);
        *reinterpret_cast<float2*>(Cf + (size_t)row * LDC + col) = make_float2(v0, v1);
    }
}

template <bool ISH, int LDC, int M>
__device__ __forceinline__ void epilogue_mat(void* C, const float* bias, const float (*cm)[4][4],
                                             int n, int row0, int col0, int wm, int wn,
                                             int g, int tig) {
    #pragma unroll
    for (int i = 0; i < 2; i++) {
        #pragma unroll
        for (int j = 0; j < 4; j++) {
            int col = col0 + wn * 32 + j * 8 + 2 * tig;
            float bv0 = bias[col], bv1 = bias[col + 1];
            int r0 = row0 + wm * 32 + i * 16 + g;
            int r1 = r0 + 8;
            if (r0 < n) store2<ISH, LDC>(C, r0, col, cm[i][j][0] + bv0, cm[i][j][1] + bv1);
            if (r1 < n) store2<ISH, LDC>(C, r1, col, cm[i][j][2] + bv0, cm[i][j][3] + bv1);
        }
    }
}

// ---------------- tf32 GEMM, dual-mat, register double-buffered -------------
#define AS_STRIDE 36
#define WS_STRIDE 72

template <int M, int TPM, int HMASK, int L0, int L1, int L2, int L3>
__global__ __launch_bounds__(256, 2)
void gemm_tf32_dual(const float* __restrict__ A,
                    const float* __restrict__ W0, const float* __restrict__ b0, void* __restrict__ C0,
                    const float* __restrict__ W1, const float* __restrict__ b1, void* __restrict__ C1,
                    const float* __restrict__ W2, const float* __restrict__ b2, void* __restrict__ C2,
                    const float* __restrict__ W3, const float* __restrict__ b3, void* __restrict__ C3,
                    int n)
{
    __shared__ float As[128 * AS_STRIDE];
    __shared__ float Ws[2][32 * WS_STRIDE];
    const int t    = threadIdx.x;
    const int warp = t >> 5, lane = t & 31;
    const int g    = lane >> 2, tig = lane & 3;
    const int wm   = warp >> 1, wn = warp & 1;
    const int row0 = blockIdx.x * 128;

    const int pair = blockIdx.y / TPM;
    const int col0 = (blockIdx.y % TPM) * 64;
    const float *WA, *WB;
    if (pair == 0) { WA = W0; WB = W1; }
    else           { WA = W2; WB = W3; }

    // per-thread load/store index precompute
    const int ar_  = t >> 3;          // A tile row       (f>>3 with l folded below)
    const int ac4_ = t & 7;           // A tile float4 col base (per l: +32 rows)
    const int wmx_ = t >> 9;          // unused placeholder
    (void)wmx_;

    float c[2][2][4][4];
    #pragma unroll
    for (int m = 0; m < 2; m++)
        #pragma unroll
        for (int i = 0; i < 2; i++)
            #pragma unroll
            for (int j = 0; j < 4; j++)
                #pragma unroll
                for (int r = 0; r < 4; r++) c[m][i][j][r] = 0.0f;

    float4 pa[4], pw[4];

    // ---- tile loaders (LDG only) and storers (cvt + STS) ----
    auto ldA = [&](int kb) {
        #pragma unroll
        for (int l = 0; l < 4; l++) {
            int f  = t + l * 256;
            int r  = f >> 3;
            int c4 = f & 7;
            int gr = row0 + r;
            float4 v = make_float4(0.f, 0.f, 0.f, 0.f);
            if (gr < n)
                v = *reinterpret_cast<const float4*>(A + (size_t)gr * 128 + kb + c4 * 4);
            pa[l] = v;
        }
    };
    auto ldW = [&](int kb) {
        #pragma unroll
        for (int l = 0; l < 4; l++) {
            int f  = t + l * 256;
            int m  = f >> 9;
            int kr = (f >> 4) & 31;
            int c4 = f & 15;
            const float* W = m ? WB : WA;
            pw[l] = *reinterpret_cast<const float4*>(W + (size_t)(kb + kr) * M + col0 + c4 * 4);
        }
    };
    auto stA = [&]() {
        #pragma unroll
        for (int l = 0; l < 4; l++) {
            int f  = t + l * 256;
            int r  = f >> 3;
            int c4 = f & 7;
            float4 v = pa[l];
            v.x = to_tf32(v.x); v.y = to_tf32(v.y); v.z = to_tf32(v.z); v.w = to_tf32(v.w);
            *reinterpret_cast<float4*>(&As[r * AS_STRIDE + c4 * 4]) = v;
        }
    };
    auto stW = [&]() {
        #pragma unroll
        for (int l = 0; l < 4; l++) {
            int f  = t + l * 256;
            int m  = f >> 9;
            int kr = (f >> 4) & 31;
            int c4 = f & 15;
            float4 v = pw[l];
            v.x = to_tf32(v.x); v.y = to_tf32(v.y); v.z = to_tf32(v.z); v.w = to_tf32(v.w);
            *reinterpret_cast<float4*>(&Ws[m][kr * WS_STRIDE + c4 * 4]) = v;
        }
    };

    // prologue: tile 0
    ldA(0); ldW(0);
    stA();  stW();
    __syncthreads();

    #pragma unroll
    for (int kbi = 0; kbi < 4; kbi++) {
        // prefetch next tile into registers (latency hidden under compute)
        if (kbi < 3) { ldA((kbi + 1) * 32); ldW((kbi + 1) * 32); }

        #pragma unroll
        for (int ks = 0; ks < 4; ks++) {
            int k0 = ks * 8;
            uint32_t bbA[4][2], bbB[4][2];
            #pragma unroll
            for (int j = 0; j < 4; j++) {
                int ncol = wn * 32 + j * 8 + g;
                bbA[j][0] = __float_as_uint(Ws[0][(k0 + tig)     * WS_STRIDE + ncol]);
                bbA[j][1] = __float_as_uint(Ws[0][(k0 + tig + 4) * WS_STRIDE + ncol]);
                bbB[j][0] = __float_as_uint(Ws[1][(k0 + tig)     * WS_STRIDE + ncol]);
                bbB[j][1] = __float_as_uint(Ws[1][(k0 + tig + 4) * WS_STRIDE + ncol]);
            }
            #pragma unroll
            for (int i = 0; i < 2; i++) {
                int ar = wm * 32 + i * 16 + g;
                uint32_t a0 = __float_as_uint(As[ar       * AS_STRIDE + k0 + tig]);
                uint32_t a1 = __float_as_uint(As[(ar + 8) * AS_STRIDE + k0 + tig]);
                uint32_t a2 = __float_as_uint(As[ar       * AS_STRIDE + k0 + tig + 4]);
                uint32_t a3 = __float_as_uint(As[(ar + 8) * AS_STRIDE + k0 + tig + 4]);
                #pragma unroll
                for (int j = 0; j < 4; j++) {
                    mma_tf32(c[0][i][j], a0, a1, a2, a3, bbA[j][0], bbA[j][1]);
                    mma_tf32(c[1][i][j], a0, a1, a2, a3, bbB[j][0], bbB[j][1]);
                }
            }
        }
        __syncthreads();
        if (kbi < 3) {
            stA(); stW();
            __syncthreads();
        }
    }

    if (pair == 0) {
        epilogue_mat<(HMASK >> 0) & 1, L0, M>(C0, b0, c[0], n, row0, col0, wm, wn, g, tig);
        epilogue_mat<(HMASK >> 1) & 1, L1, M>(C1, b1, c[1], n, row0, col0, wm, wn, g, tig);
    } else {
        epilogue_mat<(HMASK >> 2) & 1, L2, M>(C2, b2, c[0], n, row0, col0, wm, wn, g, tig);
        epilogue_mat<(HMASK >> 3) & 1, L3, M>(C3, b3, c[1], n, row0, col0, wm, wn, g, tig);
    }
}

// ---------------- fp16 helpers ----------------------------------------------
__device__ __forceinline__ void cvt8(const uint4& r, float f[8]) {
    float2 a = __half22float2(*reinterpret_cast<const __half2*>(&r.x));
    float2 b = __half22float2(*reinterpret_cast<const __half2*>(&r.y));
    float2 c = __half22float2(*reinterpret_cast<const __half2*>(&r.z));
    float2 d = __half22float2(*reinterpret_cast<const __half2*>(&r.w));
    f[0]=a.x; f[1]=a.y; f[2]=b.x; f[3]=b.y; f[4]=c.x; f[5]=c.y; f[6]=d.x; f[7]=d.y;
}

// ---------------- layer 1 attention: warp/node, pipelined kv loads ----------
__global__ void attn1() {
    int w = (blockIdx.x * blockDim.x + threadIdx.x) >> 5;
    if (w >= NN) return;
    int lane = threadIdx.x & 31;
    bool isV = lane >= 16;
    int beg = w * SLOT;
    int end = beg + g_cnt[w];

    float q[8];
    if (!isV) {
        float4 a = *reinterpret_cast<const float4*>(g_q1 + w * 128 + lane * 8);
        float4 b = *reinterpret_cast<const float4*>(g_q1 + w * 128 + lane * 8 + 4);
        q[0]=a.x*0.25f; q[1]=a.y*0.25f; q[2]=a.z*0.25f; q[3]=a.w*0.25f;
        q[4]=b.x*0.25f; q[5]=b.y*0.25f; q[6]=b.z*0.25f; q[7]=b.w*0.25f;
    } else {
        #pragma unroll
        for (int i = 0; i < 8; i++) q[i] = 0.0f;
    }

    float acc[8];
    #pragma unroll
    for (int i = 0; i < 8; i++) acc[i] = 0.0f;
    float s = 0.0f;

    if (beg < end) {
        int i0 = g_csr[beg];
        int i1 = (beg + 1 < end) ? g_csr[beg + 1] : 0;
        uint4 r0 = *reinterpret_cast<const uint4*>(g_kv1 + i0 * 256 + lane * 8);
        uint4 r1 = *reinterpret_cast<const uint4*>(g_kv1 + i1 * 256 + lane * 8);
        for (int j = beg; j < end; ) {
            int jn = j + 2;
            int i2 = (jn < end)     ? g_csr[jn]     : 0;
            int i3 = (jn + 1 < end) ? g_csr[jn + 1] : 0;
            uint4 nr0 = *reinterpret_cast<const uint4*>(g_kv1 + i2 * 256 + lane * 8);
            uint4 nr1 = *reinterpret_cast<const uint4*>(g_kv1 + i3 * 256 + lane * 8);
            float f0[8], f1[8];
            cvt8(r0, f0); cvt8(r1, f1);
            float d0 = 0.f, d1 = 0.f;
            #pragma unroll
            for (int i = 0; i < 8; i++) { d0 = fmaf(q[i], f0[i], d0); d1 = fmaf(q[i], f1[i], d1); }
            d0 += __shfl_xor_sync(0xFFFFFFFFu, d0, 1);
            d1 += __shfl_xor_sync(0xFFFFFFFFu, d1, 1);
            float t0 = __shfl_xor_sync(0xFFFFFFFFu, d0, 16);
            float t1 = __shfl_xor_sync(0xFFFFFFFFu, d1, 16);
            float p0 = __expf(t0);
            float p1 = (j + 1 < end) ? __expf(t1) : 0.0f;
            s += p0 + p1;
            #pragma unroll
            for (int i = 0; i < 8; i++) acc[i] = fmaf(p0, f0[i], fmaf(p1, f1[i], acc[i]));
            r0 = nr0; r1 = nr1;
            j = jn;
        }
    }
    if (isV) {
        int l = lane - 16;
        float inv = 1.0f / (s + 1e-16f);
        float4 sa = *reinterpret_cast<const float4*>(g_sk1 + w * 128 + l * 8);
        float4 sb = *reinterpret_cast<const float4*>(g_sk1 + w * 128 + l * 8 + 4);
        float4 o1, o2;
        o1.x = fmaxf(fmaf(acc[0], inv, sa.x), 0.0f);
        o1.y = fmaxf(fmaf(acc[1], inv, sa.y), 0.0f);
        o1.z = fmaxf(fmaf(acc[2], inv, sa.z), 0.0f);
        o1.w = fmaxf(fmaf(acc[3], inv, sa.w), 0.0f);
        o2.x = fmaxf(fmaf(acc[4], inv, sb.x), 0.0f);
        o2.y = fmaxf(fmaf(acc[5], inv, sb.y), 0.0f);
        o2.z = fmaxf(fmaf(acc[6], inv, sb.z), 0.0f);
        o2.w = fmaxf(fmaf(acc[7], inv, sb.w), 0.0f);
        *reinterpret_cast<float4*>(g_h + w * 128 + l * 8)     = o1;
        *reinterpret_cast<float4*>(g_h + w * 128 + l * 8 + 4) = o2;
    }
}

// ---------------- layer 2 attention: 16-lane group/node, pipelined ----------
__global__ void attn2(float* __restrict__ out) {
    int gt = blockIdx.x * blockDim.x + threadIdx.x;
    int w  = gt >> 4;
    if (w >= NN) return;
    int l16 = threadIdx.x & 15;
    bool isV = l16 >= 8;
    int l8 = l16 & 7;
    int beg = w * SLOT;
    int end = beg + g_cnt[w];

    float q[8];
    if (!isV) {
        float4 a = *reinterpret_cast<const float4*>(g_q2 + w * 64 + l16 * 8);
        float4 b = *reinterpret_cast<const float4*>(g_q2 + w * 64 + l16 * 8 + 4);
        q[0]=a.x*0.125f; q[1]=a.y*0.125f; q[2]=a.z*0.125f; q[3]=a.w*0.125f;
        q[4]=b.x*0.125f; q[5]=b.y*0.125f; q[6]=b.z*0.125f; q[7]=b.w*0.125f;
    } else {
        #pragma unroll
        for (int i = 0; i < 8; i++) q[i] = 0.0f;
    }

    float acc[8];
    #pragma unroll
    for (int i = 0; i < 8; i++) acc[i] = 0.0f;
    float s = 0.0f;

    if (beg < end) {
        int i0 = g_csr[beg];
        int i1 = (beg + 1 < end) ? g_csr[beg + 1] : 0;
        uint4 r0 = *reinterpret_cast<const uint4*>(g_kv2 + i0 * 128 + l16 * 8);
        uint4 r1 = *reinterpret_cast<const uint4*>(g_kv2 + i1 * 128 + l16 * 8);
        for (int j = beg; j < end; ) {
            int jn = j + 2;
            int i2 = (jn < end)     ? g_csr[jn]     : 0;
            int i3 = (jn + 1 < end) ? g_csr[jn + 1] : 0;
            uint4 nr0 = *reinterpret_cast<const uint4*>(g_kv2 + i2 * 128 + l16 * 8);
            uint4 nr1 = *reinterpret_cast<const uint4*>(g_kv2 + i3 * 128 + l16 * 8);
            float f0[8], f1[8];
            cvt8(r0, f0); cvt8(r1, f1);
            float d0 = 0.f, d1 = 0.f;
            #pragma unroll
            for (int i = 0; i < 8; i++) { d0 = fmaf(q[i], f0[i], d0); d1 = fmaf(q[i], f1[i], d1); }
            d0 += __shfl_xor_sync(0xFFFFFFFFu, d0, 1, 16);
            d1 += __shfl_xor_sync(0xFFFFFFFFu, d1, 1, 16);
            d0 += __shfl_xor_sync(0xFFFFFFFFu, d0, 2, 16);
            d1 += __shfl_xor_sync(0xFFFFFFFFu, d1, 2, 16);
            d0 += __shfl_xor_sync(0xFFFFFFFFu, d0, 4, 16);
            d1 += __shfl_xor_sync(0xFFFFFFFFu, d1, 4, 16);
            float t0 = __shfl_xor_sync(0xFFFFFFFFu, d0, 8, 16);
            float t1 = __shfl_xor_sync(0xFFFFFFFFu, d1, 8, 16);
            float p0 = __expf(t0);
            float p1 = (j + 1 < end) ? __expf(t1) : 0.0f;
            s += p0 + p1;
            #pragma unroll
            for (int i = 0; i < 8; i++) acc[i] = fmaf(p0, f0[i], fmaf(p1, f1[i], acc[i]));
            r0 = nr0; r1 = nr1;
            j = jn;
        }
    }
    if (isV) {
        float inv = 1.0f / (s + 1e-16f);
        float4 sa = *reinterpret_cast<const float4*>(g_sk2 + w * 64 + l8 * 8);
        float4 sb = *reinterpret_cast<const float4*>(g_sk2 + w * 64 + l8 * 8 + 4);
        float4 o1, o2;
        o1.x = fmaf(acc[0], inv, sa.x);
        o1.y = fmaf(acc[1], inv, sa.y);
        o1.z = fmaf(acc[2], inv, sa.z);
        o1.w = fmaf(acc[3], inv, sa.w);
        o2.x = fmaf(acc[4], inv, sb.x);
        o2.y = fmaf(acc[5], inv, sb.y);
        o2.z = fmaf(acc[6], inv, sb.z);
        o2.w = fmaf(acc[7], inv, sb.w);
        *reinterpret_cast<float4*>(out + w * 64 + l8 * 8)     = o1;
        *reinterpret_cast<float4*>(out + w * 64 + l8 * 8 + 4) = o2;
    }
}

// ---------------- launch ----------------------------------------------------
extern "C" void kernel_launch(void* const* d_in, const int* in_sizes, int n_in,
                              void* d_out, int out_size)
{
    const float* x   = (const float*)d_in[0];
    const float* Wq1 = (const float*)d_in[1];  const float* bq1 = (const float*)d_in[2];
    const float* Wk1 = (const float*)d_in[3];  const float* bk1 = (const float*)d_in[4];
    const float* Wv1 = (const float*)d_in[5];  const float* bv1 = (const float*)d_in[6];
    const float* Ws1 = (const float*)d_in[7];  const float* bs1 = (const float*)d_in[8];
    const float* Wq2 = (const float*)d_in[9];  const float* bq2 = (const float*)d_in[10];
    const float* Wk2 = (const float*)d_in[11]; const float* bk2 = (const float*)d_in[12];
    const float* Wv2 = (const float*)d_in[13]; const float* bv2 = (const float*)d_in[14];
    const float* Ws2 = (const float*)d_in[15]; const float* bs2 = (const float*)d_in[16];
    const int* esrc  = (const int*)d_in[17];
    const int* edst  = (const int*)d_in[18];
    float* out = (float*)d_out;

    void *q1, *kv1, *sk1, *h, *q2, *kv2, *sk2, *cntPtr;
    cudaGetSymbolAddress(&q1,  g_q1);
    cudaGetSymbolAddress(&kv1, g_kv1);
    cudaGetSymbolAddress(&sk1, g_sk1);
    cudaGetSymbolAddress(&h,   g_h);
    cudaGetSymbolAddress(&q2,  g_q2);
    cudaGetSymbolAddress(&kv2, g_kv2);
    cudaGetSymbolAddress(&sk2, g_sk2);
    cudaGetSymbolAddress(&cntPtr, g_cnt);

    __half* kv1h = (__half*)kv1;
    __half* kv2h = (__half*)kv2;

    const int rows = (NN + 127) / 128;                 // 391
    const int TB = 256;

    // ---- CSR build: memset counters + single fixed-stride scatter pass
    cudaMemsetAsync(cntPtr, 0, NN * sizeof(int), 0);
    csr_scatter4<<<(EE / 4 + TB - 1) / TB, TB>>>((const int4*)esrc, (const int4*)edst);

    // ---- layer 1: pair0 = {q, sk} fp32, pair1 = {k, v} fp16 interleaved
    gemm_tf32_dual<128, 2, 0xC, 128, 128, 256, 256><<<dim3(rows, 4), TB>>>(x,
        Wq1, bq1, q1,          Ws1, bs1, sk1,
        Wk1, bk1, kv1h,        Wv1, bv1, kv1h + 128,
        NN);
    attn1<<<(NN * 32 + TB - 1) / TB, TB>>>();

    // ---- layer 2
    gemm_tf32_dual<64, 1, 0xC, 64, 64, 128, 128><<<dim3(rows, 2), TB>>>((const float*)h,
        Wq2, bq2, q2,          Ws2, bs2, sk2,
        Wk2, bk2, kv2h,        Wv2, bv2, kv2h + 64,
        NN);
    attn2<<<(NN * 16 + TB - 1) / TB, TB>>>(out);
}

// round 16
// speedup vs baseline: 1.0851x; 1.0851x over previous
#include <cuda_runtime.h>
#include <cuda_fp16.h>
#include <cstdint>

#define NN 50000
#define EE 800000
#define SLOT 96          // fixed CSR slots per node; P(deg>=96) ~ 1e-40 at mean 16

// ---------------- scratch (device globals) ----------------------------------
__device__ __align__(16) float  g_q1 [NN*128];
__device__ __align__(16) __half g_kv1[NN*256];   // per node: k[0..127] | v[0..127]
__device__ __align__(16) float  g_sk1[NN*128];
__device__ __align__(16) float  g_h  [NN*128];
__device__ __align__(16) float  g_q2 [NN*64];
__device__ __align__(16) __half g_kv2[NN*128];   // per node: k[0..63] | v[0..63]
__device__ __align__(16) float  g_sk2[NN*64];
__device__ __align__(16) int g_cnt[NN];
__device__ int g_csr[NN * SLOT];   // src ids, bucketed by dst (zero-init -> always in [0,NN))

// ---------------- CSR build: memset + ONE scatter pass -----------------------
__global__ void csr_scatter4(const int4* __restrict__ src4, const int4* __restrict__ dst4) {
    int i = blockIdx.x * blockDim.x + threadIdx.x;
    if (i >= EE / 4) return;
    int4 s = src4[i];
    int4 d = dst4[i];
    g_csr[d.x * SLOT + atomicAdd(&g_cnt[d.x], 1)] = s.x;
    g_csr[d.y * SLOT + atomicAdd(&g_cnt[d.y], 1)] = s.y;
    g_csr[d.z * SLOT + atomicAdd(&g_cnt[d.z], 1)] = s.z;
    g_csr[d.w * SLOT + atomicAdd(&g_cnt[d.w], 1)] = s.w;
}

// ---------------- tf32 helpers ----------------------------------------------
__device__ __forceinline__ float to_tf32(float x) {
    uint32_t u;
    asm("cvt.rna.tf32.f32 %0, %1;" : "=r"(u) : "f"(x));
    return __uint_as_float(u);
}
__device__ __forceinline__ void mma_tf32(float c[4],
                                         uint32_t a0, uint32_t a1, uint32_t a2, uint32_t a3,
                                         uint32_t b0, uint32_t b1) {
    asm volatile("mma.sync.aligned.m16n8k8.row.col.f32.tf32.tf32.f32 "
                 "{%0,%1,%2,%3}, {%4,%5,%6,%7}, {%8,%9}, {%0,%1,%2,%3};"
                 : "+f"(c[0]), "+f"(c[1]), "+f"(c[2]), "+f"(c[3])
                 : "r"(a0), "r"(a1), "r"(a2), "r"(a3), "r"(b0), "r"(b1));
}

// ---------------- compile-time epilogue store -------------------------------
template <bool ISH, int LDC>
__device__ __forceinline__ void store2(void* C, int row, int col, float v0, float v1) {
    if (ISH) {
        __half* Ch = reinterpret_cast<__half*>(C);
        *reinterpret_cast<__half2*>(Ch + (size_t)row * LDC + col) = __floats2half2_rn(v0, v1);
    } else {
        float* Cf = reinterpret_cast<float*>(C);
        *reinterpret_cast<float2*>(Cf + (size_t)row * LDC + col) = make_float2(v0, v1);
    }
}

template <bool ISH, int LDC>
__device__ __forceinline__ void epilogue_mat(void* C, const float* bias, const float (*cm)[4][4],
                                             int n, int row0, int col0, int wm, int wn,
                                             int g, int tig) {
    #pragma unroll
    for (int i = 0; i < 2; i++) {
        #pragma unroll
        for (int j = 0; j < 4; j++) {
            int col = col0 + wn * 32 + j * 8 + 2 * tig;
            float bv0 = bias[col], bv1 = bias[col + 1];
            int r0 = row0 + wm * 32 + i * 16 + g;
            int r1 = r0 + 8;
            if (r0 < n) store2<ISH, LDC>(C, r0, col, cm[i][j][0] + bv0, cm[i][j][1] + bv1);
            if (r1 < n) store2<ISH, LDC>(C, r1, col, cm[i][j][2] + bv0, cm[i][j][3] + bv1);
        }
    }
}

// ---------------- tf32 GEMM, one weight mat per block (low regs, 3 CTA/SM) --
// BM=128, BN=64, BK=32; 8 warps as 4(m) x 2(n), 32x32 warp tile, 32 accum regs.
// grid.y = 4 * TPM: mat = y / TPM, col tile = y % TPM.
#define AS_STRIDE 36
#define WS_STRIDE 72

template <int M, int TPM, int HMASK, int L0, int L1, int L2, int L3>
__global__ __launch_bounds__(256)
void gemm_tf32_quad(const float* __restrict__ A,
                    const float* __restrict__ W0, const float* __restrict__ b0, void* __restrict__ C0,
                    const float* __restrict__ W1, const float* __restrict__ b1, void* __restrict__ C1,
                    const float* __restrict__ W2, const float* __restrict__ b2, void* __restrict__ C2,
                    const float* __restrict__ W3, const float* __restrict__ b3, void* __restrict__ C3,
                    int n)
{
    __shared__ float As[128 * AS_STRIDE];
    __shared__ float Ws[32 * WS_STRIDE];
    const int t    = threadIdx.x;
    const int warp = t >> 5, lane = t & 31;
    const int g    = lane >> 2, tig = lane & 3;
    const int wm   = warp >> 1, wn = warp & 1;
    const int row0 = blockIdx.x * 128;

    const int mat  = blockIdx.y / TPM;
    const int col0 = (blockIdx.y % TPM) * 64;
    const float* W;
    if      (mat == 0) W = W0;
    else if (mat == 1) W = W1;
    else if (mat == 2) W = W2;
    else               W = W3;

    float c[2][4][4];
    #pragma unroll
    for (int i = 0; i < 2; i++)
        #pragma unroll
        for (int j = 0; j < 4; j++)
            #pragma unroll
            for (int r = 0; r < 4; r++) c[i][j][r] = 0.0f;

    for (int kb = 0; kb < 128; kb += 32) {
        // A tile: 128x32 floats = 1024 float4, 4 per thread (tf32-converted)
        #pragma unroll
        for (int l = 0; l < 4; l++) {
            int f  = t + l * 256;
            int r  = f >> 3;
            int c4 = f & 7;
            int gr = row0 + r;
            float4 v = make_float4(0.f, 0.f, 0.f, 0.f);
            if (gr < n)
                v = *reinterpret_cast<const float4*>(A + (size_t)gr * 128 + kb + c4 * 4);
            v.x = to_tf32(v.x); v.y = to_tf32(v.y); v.z = to_tf32(v.z); v.w = to_tf32(v.w);
            *reinterpret_cast<float4*>(&As[r * AS_STRIDE + c4 * 4]) = v;
        }
        // W tile: 32x64 floats = 512 float4, 2 per thread
        #pragma unroll
        for (int l = 0; l < 2; l++) {
            int f  = t + l * 256;
            int kr = f >> 4;
            int c4 = f & 15;
            float4 v = *reinterpret_cast<const float4*>(W + (size_t)(kb + kr) * M + col0 + c4 * 4);
            v.x = to_tf32(v.x); v.y = to_tf32(v.y); v.z = to_tf32(v.z); v.w = to_tf32(v.w);
            *reinterpret_cast<float4*>(&Ws[kr * WS_STRIDE + c4 * 4]) = v;
        }
        __syncthreads();

        #pragma unroll
        for (int ks = 0; ks < 4; ks++) {
            int k0 = ks * 8;
            uint32_t bb[4][2];
            #pragma unroll
            for (int j = 0; j < 4; j++) {
                int ncol = wn * 32 + j * 8 + g;
                bb[j][0] = __float_as_uint(Ws[(k0 + tig)     * WS_STRIDE + ncol]);
                bb[j][1] = __float_as_uint(Ws[(k0 + tig + 4) * WS_STRIDE + ncol]);
            }
            #pragma unroll
            for (int i = 0; i < 2; i++) {
                int ar = wm * 32 + i * 16 + g;
                uint32_t a0 = __float_as_uint(As[ar       * AS_STRIDE + k0 + tig]);
                uint32_t a1 = __float_as_uint(As[(ar + 8) * AS_STRIDE + k0 + tig]);
                uint32_t a2 = __float_as_uint(As[ar       * AS_STRIDE + k0 + tig + 4]);
                uint32_t a3 = __float_as_uint(As[(ar + 8) * AS_STRIDE + k0 + tig + 4]);
                #pragma unroll
                for (int j = 0; j < 4; j++)
                    mma_tf32(c[i][j], a0, a1, a2, a3, bb[j][0], bb[j][1]);
            }
        }
        __syncthreads();
    }

    if      (mat == 0) epilogue_mat<(HMASK >> 0) & 1, L0>(C0, b0, c, n, row0, col0, wm, wn, g, tig);
    else if (mat == 1) epilogue_mat<(HMASK >> 1) & 1, L1>(C1, b1, c, n, row0, col0, wm, wn, g, tig);
    else if (mat == 2) epilogue_mat<(HMASK >> 2) & 1, L2>(C2, b2, c, n, row0, col0, wm, wn, g, tig);
    else               epilogue_mat<(HMASK >> 3) & 1, L3>(C3, b3, c, n, row0, col0, wm, wn, g, tig);
}

// ---------------- fp16 helpers ----------------------------------------------
__device__ __forceinline__ void cvt8(const uint4& r, float f[8]) {
    float2 a = __half22float2(*reinterpret_cast<const __half2*>(&r.x));
    float2 b = __half22float2(*reinterpret_cast<const __half2*>(&r.y));
    float2 c = __half22float2(*reinterpret_cast<const __half2*>(&r.z));
    float2 d = __half22float2(*reinterpret_cast<const __half2*>(&r.w));
    f[0]=a.x; f[1]=a.y; f[2]=b.x; f[3]=b.y; f[4]=c.x; f[5]=c.y; f[6]=d.x; f[7]=d.y;
}

// ---------------- layer 1 attention: warp/node, pipelined kv loads ----------
__global__ void attn1() {
    int w = (blockIdx.x * blockDim.x + threadIdx.x) >> 5;
    if (w >= NN) return;
    int lane = threadIdx.x & 31;
    bool isV = lane >= 16;
    int beg = w * SLOT;
    int end = beg + g_cnt[w];

    float q[8];
    if (!isV) {
        float4 a = *reinterpret_cast<const float4*>(g_q1 + w * 128 + lane * 8);
        float4 b = *reinterpret_cast<const float4*>(g_q1 + w * 128 + lane * 8 + 4);
        q[0]=a.x*0.25f; q[1]=a.y*0.25f; q[2]=a.z*0.25f; q[3]=a.w*0.25f;
        q[4]=b.x*0.25f; q[5]=b.y*0.25f; q[6]=b.z*0.25f; q[7]=b.w*0.25f;
    } else {
        #pragma unroll
        for (int i = 0; i < 8; i++) q[i] = 0.0f;
    }

    float acc[8];
    #pragma unroll
    for (int i = 0; i < 8; i++) acc[i] = 0.0f;
    float s = 0.0f;

    if (beg < end) {
        int i0 = g_csr[beg];
        int i1 = (beg + 1 < end) ? g_csr[beg + 1] : 0;
        uint4 r0 = *reinterpret_cast<const uint4*>(g_kv1 + i0 * 256 + lane * 8);
        uint4 r1 = *reinterpret_cast<const uint4*>(g_kv1 + i1 * 256 + lane * 8);
        for (int j = beg; j < end; ) {
            int jn = j + 2;
            int i2 = (jn < end)     ? g_csr[jn]     : 0;
            int i3 = (jn + 1 < end) ? g_csr[jn + 1] : 0;
            uint4 nr0 = *reinterpret_cast<const uint4*>(g_kv1 + i2 * 256 + lane * 8);
            uint4 nr1 = *reinterpret_cast<const uint4*>(g_kv1 + i3 * 256 + lane * 8);
            float f0[8], f1[8];
            cvt8(r0, f0); cvt8(r1, f1);
            float d0 = 0.f, d1 = 0.f;
            #pragma unroll
            for (int i = 0; i < 8; i++) { d0 = fmaf(q[i], f0[i], d0); d1 = fmaf(q[i], f1[i], d1); }
            d0 += __shfl_xor_sync(0xFFFFFFFFu, d0, 1);
            d1 += __shfl_xor_sync(0xFFFFFFFFu, d1, 1);
            float t0 = __shfl_xor_sync(0xFFFFFFFFu, d0, 16);
            float t1 = __shfl_xor_sync(0xFFFFFFFFu, d1, 16);
            float p0 = __expf(t0);
            float p1 = (j + 1 < end) ? __expf(t1) : 0.0f;
            s += p0 + p1;
            #pragma unroll
            for (int i = 0; i < 8; i++) acc[i] = fmaf(p0, f0[i], fmaf(p1, f1[i], acc[i]));
            r0 = nr0; r1 = nr1;
            j = jn;
        }
    }
    if (isV) {
        int l = lane - 16;
        float inv = 1.0f / (s + 1e-16f);
        float4 sa = *reinterpret_cast<const float4*>(g_sk1 + w * 128 + l * 8);
        float4 sb = *reinterpret_cast<const float4*>(g_sk1 + w * 128 + l * 8 + 4);
        float4 o1, o2;
        o1.x = fmaxf(fmaf(acc[0], inv, sa.x), 0.0f);
        o1.y = fmaxf(fmaf(acc[1], inv, sa.y), 0.0f);
        o1.z = fmaxf(fmaf(acc[2], inv, sa.z), 0.0f);
        o1.w = fmaxf(fmaf(acc[3], inv, sa.w), 0.0f);
        o2.x = fmaxf(fmaf(acc[4], inv, sb.x), 0.0f);
        o2.y = fmaxf(fmaf(acc[5], inv, sb.y), 0.0f);
        o2.z = fmaxf(fmaf(acc[6], inv, sb.z), 0.0f);
        o2.w = fmaxf(fmaf(acc[7], inv, sb.w), 0.0f);
        *reinterpret_cast<float4*>(g_h + w * 128 + l * 8)     = o1;
        *reinterpret_cast<float4*>(g_h + w * 128 + l * 8 + 4) = o2;
    }
}

// ---------------- layer 2 attention: 16-lane group/node, pipelined ----------
__global__ void attn2(float* __restrict__ out) {
    int gt = blockIdx.x * blockDim.x + threadIdx.x;
    int w  = gt >> 4;
    if (w >= NN) return;
    int l16 = threadIdx.x & 15;
    bool isV = l16 >= 8;
    int l8 = l16 & 7;
    int beg = w * SLOT;
    int end = beg + g_cnt[w];

    float q[8];
    if (!isV) {
        float4 a = *reinterpret_cast<const float4*>(g_q2 + w * 64 + l16 * 8);
        float4 b = *reinterpret_cast<const float4*>(g_q2 + w * 64 + l16 * 8 + 4);
        q[0]=a.x*0.125f; q[1]=a.y*0.125f; q[2]=a.z*0.125f; q[3]=a.w*0.125f;
        q[4]=b.x*0.125f; q[5]=b.y*0.125f; q[6]=b.z*0.125f; q[7]=b.w*0.125f;
    } else {
        #pragma unroll
        for (int i = 0; i < 8; i++) q[i] = 0.0f;
    }

    float acc[8];
    #pragma unroll
    for (int i = 0; i < 8; i++) acc[i] = 0.0f;
    float s = 0.0f;

    if (beg < end) {
        int i0 = g_csr[beg];
        int i1 = (beg + 1 < end) ? g_csr[beg + 1] : 0;
        uint4 r0 = *reinterpret_cast<const uint4*>(g_kv2 + i0 * 128 + l16 * 8);
        uint4 r1 = *reinterpret_cast<const uint4*>(g_kv2 + i1 * 128 + l16 * 8);
        for (int j = beg; j < end; ) {
            int jn = j + 2;
            int i2 = (jn < end)     ? g_csr[jn]     : 0;
            int i3 = (jn + 1 < end) ? g_csr[jn + 1] : 0;
            uint4 nr0 = *reinterpret_cast<const uint4*>(g_kv2 + i2 * 128 + l16 * 8);
            uint4 nr1 = *reinterpret_cast<const uint4*>(g_kv2 + i3 * 128 + l16 * 8);
            float f0[8], f1[8];
            cvt8(r0, f0); cvt8(r1, f1);
            float d0 = 0.f, d1 = 0.f;
            #pragma unroll
            for (int i = 0; i < 8; i++) { d0 = fmaf(q[i], f0[i], d0); d1 = fmaf(q[i], f1[i], d1); }
            d0 += __shfl_xor_sync(0xFFFFFFFFu, d0, 1, 16);
            d1 += __shfl_xor_sync(0xFFFFFFFFu, d1, 1, 16);
            d0 += __shfl_xor_sync(0xFFFFFFFFu, d0, 2, 16);
            d1 += __shfl_xor_sync(0xFFFFFFFFu, d1, 2, 16);
            d0 += __shfl_xor_sync(0xFFFFFFFFu, d0, 4, 16);
            d1 += __shfl_xor_sync(0xFFFFFFFFu, d1, 4, 16);
            float t0 = __shfl_xor_sync(0xFFFFFFFFu, d0, 8, 16);
            float t1 = __shfl_xor_sync(0xFFFFFFFFu, d1, 8, 16);
            float p0 = __expf(t0);
            float p1 = (j + 1 < end) ? __expf(t1) : 0.0f;
            s += p0 + p1;
            #pragma unroll
            for (int i = 0; i < 8; i++) acc[i] = fmaf(p0, f0[i], fmaf(p1, f1[i], acc[i]));
            r0 = nr0; r1 = nr1;
            j = jn;
        }
    }
    if (isV) {
        float inv = 1.0f / (s + 1e-16f);
        float4 sa = *reinterpret_cast<const float4*>(g_sk2 + w * 64 + l8 * 8);
        float4 sb = *reinterpret_cast<const float4*>(g_sk2 + w * 64 + l8 * 8 + 4);
        float4 o1, o2;
        o1.x = fmaf(acc[0], inv, sa.x);
        o1.y = fmaf(acc[1], inv, sa.y);
        o1.z = fmaf(acc[2], inv, sa.z);
        o1.w = fmaf(acc[3], inv, sa.w);
        o2.x = fmaf(acc[4], inv, sb.x);
        o2.y = fmaf(acc[5], inv, sb.y);
        o2.z = fmaf(acc[6], inv, sb.z);
        o2.w = fmaf(acc[7], inv, sb.w);
        *reinterpret_cast<float4*>(out + w * 64 + l8 * 8)     = o1;
        *reinterpret_cast<float4*>(out + w * 64 + l8 * 8 + 4) = o2;
    }
}

// ---------------- launch ----------------------------------------------------
extern "C" void kernel_launch(void* const* d_in, const int* in_sizes, int n_in,
                              void* d_out, int out_size)
{
    const float* x   = (const float*)d_in[0];
    const float* Wq1 = (const float*)d_in[1];  const float* bq1 = (const float*)d_in[2];
    const float* Wk1 = (const float*)d_in[3];  const float* bk1 = (const float*)d_in[4];
    const float* Wv1 = (const float*)d_in[5];  const float* bv1 = (const float*)d_in[6];
    const float* Ws1 = (const float*)d_in[7];  const float* bs1 = (const float*)d_in[8];
    const float* Wq2 = (const float*)d_in[9];  const float* bq2 = (const float*)d_in[10];
    const float* Wk2 = (const float*)d_in[11]; const float* bk2 = (const float*)d_in[12];
    const float* Wv2 = (const float*)d_in[13]; const float* bv2 = (const float*)d_in[14];
    const float* Ws2 = (const float*)d_in[15]; const float* bs2 = (const float*)d_in[16];
    const int* esrc  = (const int*)d_in[17];
    const int* edst  = (const int*)d_in[18];
    float* out = (float*)d_out;

    void *q1, *kv1, *sk1, *h, *q2, *kv2, *sk2, *cntPtr;
    cudaGetSymbolAddress(&q1,  g_q1);
    cudaGetSymbolAddress(&kv1, g_kv1);
    cudaGetSymbolAddress(&sk1, g_sk1);
    cudaGetSymbolAddress(&h,   g_h);
    cudaGetSymbolAddress(&q2,  g_q2);
    cudaGetSymbolAddress(&kv2, g_kv2);
    cudaGetSymbolAddress(&sk2, g_sk2);
    cudaGetSymbolAddress(&cntPtr, g_cnt);

    __half* kv1h = (__half*)kv1;
    __half* kv2h = (__half*)kv2;

    const int rows = (NN + 127) / 128;                 // 391
    const int TB = 256;

    // ---- CSR build: memset counters + single fixed-stride scatter pass
    cudaMemsetAsync(cntPtr, 0, NN * sizeof(int), 0);
    csr_scatter4<<<(EE / 4 + TB - 1) / TB, TB>>>((const int4*)esrc, (const int4*)edst);

    // ---- layer 1: mats {q(f32), sk(f32), k(h16), v(h16)} -> grid.y = 4*2
    gemm_tf32_quad<128, 2, 0xC, 128, 128, 256, 256><<<dim3(rows, 8), TB>>>(x,
        Wq1, bq1, q1,          Ws1, bs1, sk1,
        Wk1, bk1, kv1h,        Wv1, bv1, kv1h + 128,
        NN);
    attn1<<<(NN * 32 + TB - 1) / TB, TB>>>();

    // ---- layer 2: grid.y = 4*1
    gemm_tf32_quad<64, 1, 0xC, 64, 64, 128, 128><<<dim3(rows, 4), TB>>>((const float*)h,
        Wq2, bq2, q2,          Ws2, bs2, sk2,
        Wk2, bk2, kv2h,        Wv2, bv2, kv2h + 64,
        NN);
    attn2<<<(NN * 16 + TB - 1) / TB, TB>>>(out);
}